// round 1
// baseline (speedup 1.0000x reference)
#include <cuda_runtime.h>
#include <cuda_bf16.h>
#include <math.h>

#define B_SZ 2
#define SEQ 2048
#define DIM 4096
#define NH 32
#define NKV 8
#define HEAD 128
#define NREP 4
#define HIDDEN 11008
#define M_TOK (B_SZ*SEQ)   // 4096

// ---------------- scratch (device globals; allocation-free rule) ----------------
__device__ float g_xq  [M_TOK * NH  * HEAD];   // 4096 x 4096
__device__ float g_xk  [M_TOK * NKV * HEAD];   // 4096 x 1024
__device__ float g_xv  [M_TOK * NKV * HEAD];   // 4096 x 1024
__device__ float g_attn[M_TOK * NH  * HEAD];   // 4096 x 4096
__device__ float g_h   [M_TOK * DIM];          // 4096 x 4096
__device__ float g_gate[M_TOK * HIDDEN];       // 4096 x 11008
__device__ float g_up  [M_TOK * HIDDEN];       // 4096 x 11008

// ---------------- generic SGEMM: C = A @ W (+ R) ----------------
// A: [M,K] row-major, W: [K,N] row-major, C/R: [M,N] row-major
// 128x128 tile, BK=8, 256 threads, 8x8 per-thread as 2x2 quads of 4x4.
template<int EPI>   // 0: C = A@W   1: C = A@W + R
__global__ __launch_bounds__(256, 2)
void sgemm_kernel(const float* __restrict__ A, const float* __restrict__ W,
                  const float* __restrict__ R, float* __restrict__ C,
                  int M, int N, int K)
{
    __shared__ float As[8][128];
    __shared__ float Bs[8][128];

    const int tid = threadIdx.x;
    const int row0 = blockIdx.y * 128;
    const int col0 = blockIdx.x * 128;

    const int arow = tid >> 1;          // 0..127
    const int ak   = (tid & 1) * 4;     // 0 or 4
    const int brow = tid >> 5;          // 0..7
    const int bcol = (tid & 31) * 4;    // 0..124

    const int tx = tid & 15;
    const int ty = tid >> 4;

    float acc[2][2][4][4];
    #pragma unroll
    for (int a = 0; a < 2; a++)
        #pragma unroll
        for (int b = 0; b < 2; b++)
            #pragma unroll
            for (int i = 0; i < 4; i++)
                #pragma unroll
                for (int j = 0; j < 4; j++) acc[a][b][i][j] = 0.f;

    const float* Aptr = A + (size_t)(row0 + arow) * K + ak;
    const float* Wptr = W + (size_t)brow * N + col0 + bcol;

    for (int k0 = 0; k0 < K; k0 += 8) {
        float4 av = *(const float4*)(Aptr + k0);
        float4 bv = *(const float4*)(Wptr + (size_t)k0 * N);
        As[ak + 0][arow] = av.x;
        As[ak + 1][arow] = av.y;
        As[ak + 2][arow] = av.z;
        As[ak + 3][arow] = av.w;
        *(float4*)&Bs[brow][bcol] = bv;
        __syncthreads();

        #pragma unroll
        for (int kk = 0; kk < 8; kk++) {
            float4 a0 = *(const float4*)&As[kk][ty * 4];
            float4 a1 = *(const float4*)&As[kk][64 + ty * 4];
            float4 b0 = *(const float4*)&Bs[kk][tx * 4];
            float4 b1 = *(const float4*)&Bs[kk][64 + tx * 4];
            float ar[2][4] = {{a0.x,a0.y,a0.z,a0.w},{a1.x,a1.y,a1.z,a1.w}};
            float br[2][4] = {{b0.x,b0.y,b0.z,b0.w},{b1.x,b1.y,b1.z,b1.w}};
            #pragma unroll
            for (int a = 0; a < 2; a++)
                #pragma unroll
                for (int i = 0; i < 4; i++)
                    #pragma unroll
                    for (int b = 0; b < 2; b++)
                        #pragma unroll
                        for (int j = 0; j < 4; j++)
                            acc[a][b][i][j] += ar[a][i] * br[b][j];
        }
        __syncthreads();
    }

    #pragma unroll
    for (int a = 0; a < 2; a++) {
        #pragma unroll
        for (int i = 0; i < 4; i++) {
            int r = row0 + a * 64 + ty * 4 + i;
            #pragma unroll
            for (int b = 0; b < 2; b++) {
                int c = col0 + b * 64 + tx * 4;
                float4 v = make_float4(acc[a][b][i][0], acc[a][b][i][1],
                                       acc[a][b][i][2], acc[a][b][i][3]);
                if (EPI == 1) {
                    float4 rv = *(const float4*)(R + (size_t)r * N + c);
                    v.x += rv.x; v.y += rv.y; v.z += rv.z; v.w += rv.w;
                }
                *(float4*)(C + (size_t)r * N + c) = v;
            }
        }
    }
}

// ---------------- RoPE (in place on q and k) ----------------
__global__ void rope_kernel(float* __restrict__ q, float* __restrict__ k,
                            const float* __restrict__ fcos, const float* __restrict__ fsin)
{
    long idx = (long)blockIdx.x * blockDim.x + threadIdx.x;
    const long total = (long)M_TOK * (NH + NKV) * (HEAD / 2);
    if (idx >= total) return;
    int j  = idx & 63;                     // pair index 0..63
    long t2 = idx >> 6;
    int hh = (int)(t2 % (NH + NKV));
    long tok = t2 / (NH + NKV);            // 0..M_TOK-1
    int s = (int)(tok % SEQ);

    float* p;
    if (hh < NH) p = q + ((size_t)tok * NH + hh) * HEAD + 2 * j;
    else         p = k + ((size_t)tok * NKV + (hh - NH)) * HEAD + 2 * j;

    float c = fcos[s * 64 + j];
    float sn = fsin[s * 64 + j];
    float x0 = p[0], x1 = p[1];
    p[0] = x0 * c - x1 * sn;
    p[1] = x0 * sn + x1 * c;
}

// ---------------- flash attention (fp32, causal, GQA) ----------------
#define QT 64
#define KT 64
#define PQK 130
#define PVS 132

__global__ __launch_bounds__(256, 1)
void flash_kernel(const float* __restrict__ Q, const float* __restrict__ K,
                  const float* __restrict__ V, float* __restrict__ O)
{
    extern __shared__ float sm[];
    float* Qs = sm;                         // 64 x 130
    float* Ks = Qs + QT * PQK;              // 64 x 130
    float* Vs = Ks + KT * PQK;              // 64 x 132
    float* Ps = Vs + KT * PVS;              // 64 x 65

    const int t  = threadIdx.x;
    const int bx = blockIdx.x;              // q tile
    const int h  = blockIdx.y;
    const int b  = blockIdx.z;
    const int kvh = h >> 2;
    const int q0 = bx * QT;
    const float scale = 0.08838834764831845f;   // 1/sqrt(128)

    // load Q tile
    {
        const float* qbase = Q + ((size_t)(b * SEQ + q0) * NH + h) * HEAD;
        for (int e = t; e < QT * 64; e += 256) {
            int r = e >> 6, cc = (e & 63) << 1;
            float2 v = *(const float2*)(qbase + (size_t)r * NH * HEAD + cc);
            Qs[r * PQK + cc]     = v.x;
            Qs[r * PQK + cc + 1] = v.y;
        }
    }

    // PV / softmax mapping: 4 threads per q-row
    const int pq = t >> 2;                  // 0..63
    const int pd = (t & 3) * 4;             // float4 chunks at pd + 16*c
    // scores mapping: 4x4 per thread
    const int sq0 = (t >> 4) * 4;           // rows sq0..sq0+3
    const int scc = t & 15;                 // cols scc + 16*m

    float m = -INFINITY, l = 0.f;
    float4 acc[8];
    #pragma unroll
    for (int c = 0; c < 8; c++) acc[c] = make_float4(0.f, 0.f, 0.f, 0.f);

    for (int j = 0; j <= bx; j++) {
        __syncthreads();   // previous tile fully consumed
        {
            const float* kbase = K + ((size_t)(b * SEQ + j * KT) * NKV + kvh) * HEAD;
            const float* vbase = V + ((size_t)(b * SEQ + j * KT) * NKV + kvh) * HEAD;
            for (int e = t; e < KT * 64; e += 256) {
                int r = e >> 6, cc = (e & 63) << 1;
                float2 kv2 = *(const float2*)(kbase + (size_t)r * NKV * HEAD + cc);
                Ks[r * PQK + cc]     = kv2.x;
                Ks[r * PQK + cc + 1] = kv2.y;
                float2 vv2 = *(const float2*)(vbase + (size_t)r * NKV * HEAD + cc);
                Vs[r * PVS + cc]     = vv2.x;
                Vs[r * PVS + cc + 1] = vv2.y;
            }
        }
        __syncthreads();

        // scores 4x4 per thread
        float s4[4][4];
        #pragma unroll
        for (int i = 0; i < 4; i++)
            #pragma unroll
            for (int mm = 0; mm < 4; mm++) s4[i][mm] = 0.f;

        for (int d = 0; d < HEAD; d++) {
            float qv[4], kv[4];
            #pragma unroll
            for (int i = 0; i < 4; i++) qv[i] = Qs[(sq0 + i) * PQK + d];
            #pragma unroll
            for (int mm = 0; mm < 4; mm++) kv[mm] = Ks[(scc + 16 * mm) * PQK + d];
            #pragma unroll
            for (int i = 0; i < 4; i++)
                #pragma unroll
                for (int mm = 0; mm < 4; mm++) s4[i][mm] += qv[i] * kv[mm];
        }
        const bool diag = (j == bx);
        #pragma unroll
        for (int i = 0; i < 4; i++) {
            #pragma unroll
            for (int mm = 0; mm < 4; mm++) {
                float sv = s4[i][mm] * scale;
                if (diag && (j * KT + scc + 16 * mm) > (q0 + sq0 + i)) sv = -1e30f;
                Ps[(sq0 + i) * 65 + scc + 16 * mm] = sv;
            }
        }
        __syncthreads();

        // online softmax for row pq (4-lane group)
        float tmax = -1e30f;
        #pragma unroll
        for (int k4 = 0; k4 < 16; k4++)
            tmax = fmaxf(tmax, Ps[pq * 65 + (t & 3) + 4 * k4]);
        tmax = fmaxf(tmax, __shfl_xor_sync(0xffffffffu, tmax, 1));
        tmax = fmaxf(tmax, __shfl_xor_sync(0xffffffffu, tmax, 2));
        float mnew = fmaxf(m, tmax);
        float psum = 0.f;
        #pragma unroll
        for (int k4 = 0; k4 < 16; k4++) {
            int si = (t & 3) + 4 * k4;
            float p = __expf(Ps[pq * 65 + si] - mnew);
            Ps[pq * 65 + si] = p;
            psum += p;
        }
        psum += __shfl_xor_sync(0xffffffffu, psum, 1);
        psum += __shfl_xor_sync(0xffffffffu, psum, 2);
        float sc_old = __expf(m - mnew);
        l = l * sc_old + psum;
        m = mnew;
        #pragma unroll
        for (int c = 0; c < 8; c++) {
            acc[c].x *= sc_old; acc[c].y *= sc_old;
            acc[c].z *= sc_old; acc[c].w *= sc_old;
        }
        __syncthreads();   // all probs written

        // PV accumulate
        for (int s = 0; s < KT; s++) {
            float p = Ps[pq * 65 + s];
            #pragma unroll
            for (int c = 0; c < 8; c++) {
                float4 v4 = *(const float4*)&Vs[s * PVS + pd + 16 * c];
                acc[c].x += p * v4.x; acc[c].y += p * v4.y;
                acc[c].z += p * v4.z; acc[c].w += p * v4.w;
            }
        }
    }

    float inv = 1.f / l;
    float* obase = O + ((size_t)(b * SEQ + q0 + pq) * NH + h) * HEAD;
    #pragma unroll
    for (int c = 0; c < 8; c++) {
        float4 v = acc[c];
        v.x *= inv; v.y *= inv; v.z *= inv; v.w *= inv;
        *(float4*)(obase + pd + 16 * c) = v;
    }
}

// ---------------- silu(gate) * up, in place into gate ----------------
__global__ void silu_mul_kernel(float* __restrict__ g, const float* __restrict__ u, long n4)
{
    long i = (long)blockIdx.x * blockDim.x + threadIdx.x;
    if (i >= n4) return;
    float4 gv = ((const float4*)g)[i];
    float4 uv = ((const float4*)u)[i];
    gv.x = gv.x / (1.f + __expf(-gv.x)) * uv.x;
    gv.y = gv.y / (1.f + __expf(-gv.y)) * uv.y;
    gv.z = gv.z / (1.f + __expf(-gv.z)) * uv.z;
    gv.w = gv.w / (1.f + __expf(-gv.w)) * uv.w;
    ((float4*)g)[i] = gv;
}

// ---------------- host launcher ----------------
extern "C" void kernel_launch(void* const* d_in, const int* in_sizes, int n_in,
                              void* d_out, int out_size)
{
    const float* x    = (const float*)d_in[0];
    // d_in[1] mask unused (causal mask applied analytically)
    const float* fcos = (const float*)d_in[2];
    const float* fsin = (const float*)d_in[3];
    const float* wq   = (const float*)d_in[4];
    const float* wk   = (const float*)d_in[5];
    const float* wv   = (const float*)d_in[6];
    const float* wo   = (const float*)d_in[7];
    const float* w1   = (const float*)d_in[8];
    const float* w2   = (const float*)d_in[9];
    const float* w3   = (const float*)d_in[10];
    float* out = (float*)d_out;

    float *xq, *xk, *xv, *attn, *h, *gate, *up;
    cudaGetSymbolAddress((void**)&xq,   g_xq);
    cudaGetSymbolAddress((void**)&xk,   g_xk);
    cudaGetSymbolAddress((void**)&xv,   g_xv);
    cudaGetSymbolAddress((void**)&attn, g_attn);
    cudaGetSymbolAddress((void**)&h,    g_h);
    cudaGetSymbolAddress((void**)&gate, g_gate);
    cudaGetSymbolAddress((void**)&up,   g_up);

    const int FL_SMEM = (QT * PQK + KT * PQK + KT * PVS + 64 * 65) * 4;
    cudaFuncSetAttribute(flash_kernel, cudaFuncAttributeMaxDynamicSharedMemorySize, FL_SMEM);

    // QKV projections
    sgemm_kernel<0><<<dim3(32, 32), 256>>>(x, wq, nullptr, xq, M_TOK, NH * HEAD, DIM);
    sgemm_kernel<0><<<dim3(8, 32), 256>>>(x, wk, nullptr, xk, M_TOK, NKV * HEAD, DIM);
    sgemm_kernel<0><<<dim3(8, 32), 256>>>(x, wv, nullptr, xv, M_TOK, NKV * HEAD, DIM);

    // RoPE
    {
        long total = (long)M_TOK * (NH + NKV) * (HEAD / 2);
        int blocks = (int)((total + 255) / 256);
        rope_kernel<<<blocks, 256>>>(xq, xk, fcos, fsin);
    }

    // attention
    flash_kernel<<<dim3(SEQ / QT, NH, B_SZ), 256, FL_SMEM>>>(xq, xk, xv, attn);

    // output projection + residual: h = x + attn @ wo
    sgemm_kernel<1><<<dim3(32, 32), 256>>>(attn, wo, x, h, M_TOK, DIM, NH * HEAD);

    // FFN
    sgemm_kernel<0><<<dim3(HIDDEN / 128, 32), 256>>>(h, w1, nullptr, gate, M_TOK, HIDDEN, DIM);
    sgemm_kernel<0><<<dim3(HIDDEN / 128, 32), 256>>>(h, w3, nullptr, up, M_TOK, HIDDEN, DIM);
    {
        long n4 = (long)M_TOK * HIDDEN / 4;
        int blocks = (int)((n4 + 255) / 256);
        silu_mul_kernel<<<blocks, 256>>>(gate, up, n4);
    }
    // out = h + (silu(g)*u) @ w2
    sgemm_kernel<1><<<dim3(32, 32), 256>>>(gate, w2, h, out, M_TOK, DIM, HIDDEN);
}

// round 8
// speedup vs baseline: 1.8734x; 1.8734x over previous
#include <cuda_runtime.h>
#include <cuda_bf16.h>
#include <math.h>
#include <stdint.h>

#define B_SZ 2
#define SEQ 2048
#define DIM 4096
#define NH 32
#define NKV 8
#define HEAD 128
#define HIDDEN 11008
#define M_TOK (B_SZ*SEQ)   // 4096

// ---------------- scratch (device globals; allocation-free rule) ----------------
__device__ float g_xq  [(size_t)M_TOK * NH  * HEAD];
__device__ float g_xk  [(size_t)M_TOK * NKV * HEAD];
__device__ float g_xv  [(size_t)M_TOK * NKV * HEAD];
__device__ float g_attn[(size_t)M_TOK * NH  * HEAD];
__device__ float g_h   [(size_t)M_TOK * DIM];
__device__ float g_gate[(size_t)M_TOK * HIDDEN];
__device__ float g_up  [(size_t)M_TOK * HIDDEN];

// transposed + split weights: T[n][k] = split(W[k][n]), bf16 hi/lo
__device__ __nv_bfloat16 g_wq_h[(size_t)DIM*NH*HEAD],  g_wq_l[(size_t)DIM*NH*HEAD];
__device__ __nv_bfloat16 g_wk_h[(size_t)DIM*NKV*HEAD], g_wk_l[(size_t)DIM*NKV*HEAD];
__device__ __nv_bfloat16 g_wv_h[(size_t)DIM*NKV*HEAD], g_wv_l[(size_t)DIM*NKV*HEAD];
__device__ __nv_bfloat16 g_wo_h[(size_t)DIM*NH*HEAD],  g_wo_l[(size_t)DIM*NH*HEAD];
__device__ __nv_bfloat16 g_w1_h[(size_t)DIM*HIDDEN],   g_w1_l[(size_t)DIM*HIDDEN];
__device__ __nv_bfloat16 g_w3_h[(size_t)DIM*HIDDEN],   g_w3_l[(size_t)DIM*HIDDEN];
__device__ __nv_bfloat16 g_w2_h[(size_t)DIM*HIDDEN],   g_w2_l[(size_t)DIM*HIDDEN];

// ---------------- helpers (sm_80-compatible only: mma.sync / ldmatrix / cp.async) ----
__device__ __forceinline__ uint32_t smem_u32(const void* p){
    uint32_t a;
    asm("{ .reg .u64 t; cvta.to.shared.u64 t, %1; cvt.u32.u64 %0, t; }" : "=r"(a) : "l"(p));
    return a;
}
__device__ __forceinline__ void cp16(uint32_t dst, const void* src){
    asm volatile("cp.async.cg.shared.global [%0], [%1], 16;" :: "r"(dst), "l"(src) : "memory");
}
#define CP_COMMIT() asm volatile("cp.async.commit_group;" ::: "memory")
#define CP_WAIT0()  asm volatile("cp.async.wait_group 0;" ::: "memory")

__device__ __forceinline__ void ldsm4(uint32_t& r0, uint32_t& r1, uint32_t& r2, uint32_t& r3, uint32_t a){
    asm volatile("ldmatrix.sync.aligned.m8n8.x4.shared.b16 {%0,%1,%2,%3}, [%4];"
                 : "=r"(r0), "=r"(r1), "=r"(r2), "=r"(r3) : "r"(a));
}
__device__ __forceinline__ void mma16816(float* c, uint32_t a0, uint32_t a1, uint32_t a2, uint32_t a3,
                                         uint32_t b0, uint32_t b1){
    asm volatile("mma.sync.aligned.m16n8k16.row.col.f32.bf16.bf16.f32 "
                 "{%0,%1,%2,%3}, {%4,%5,%6,%7}, {%8,%9}, {%0,%1,%2,%3};"
                 : "+f"(c[0]), "+f"(c[1]), "+f"(c[2]), "+f"(c[3])
                 : "r"(a0), "r"(a1), "r"(a2), "r"(a3), "r"(b0), "r"(b1));
}
__device__ __forceinline__ void split2(float x, float y, uint32_t& h, uint32_t& l){
    __nv_bfloat16 hx = __float2bfloat16(x), hy = __float2bfloat16(y);
    float rx = x - __bfloat162float(hx), ry = y - __bfloat162float(hy);
    __nv_bfloat16 lx = __float2bfloat16(rx), ly = __float2bfloat16(ry);
    h = ((uint32_t)__bfloat16_as_ushort(hy) << 16) | __bfloat16_as_ushort(hx);
    l = ((uint32_t)__bfloat16_as_ushort(ly) << 16) | __bfloat16_as_ushort(lx);
}
// tile layout: 128 logical rows x 64B (32 bf16). Pairs of rows share one 128B
// physical row; swizzle XORs bits [4:6] of the offset with phys-row bits.
__device__ __forceinline__ uint32_t tile_off(int r, int byte_in_row){
    uint32_t o = ((uint32_t)(r >> 1) << 7) + ((uint32_t)(r & 1) << 6) + (uint32_t)byte_in_row;
    return o ^ ((o >> 3) & 0x70);
}

// ---------------- weight transpose + hi/lo split ----------------
__global__ void conv_w_kernel(const float* __restrict__ W, __nv_bfloat16* __restrict__ Th,
                              __nv_bfloat16* __restrict__ Tl, int K, int N)
{
    __shared__ float tile[32][33];
    int n0 = blockIdx.x * 32, k0 = blockIdx.y * 32;
    int tx = threadIdx.x, ty = threadIdx.y;   // 32 x 8
    #pragma unroll
    for (int r = 0; r < 32; r += 8)
        tile[ty + r][tx] = W[(size_t)(k0 + ty + r) * N + n0 + tx];
    __syncthreads();
    #pragma unroll
    for (int r = 0; r < 32; r += 8) {
        int n = n0 + ty + r;
        int k = k0 + tx;
        float v = tile[tx][ty + r];
        __nv_bfloat16 h = __float2bfloat16(v);
        __nv_bfloat16 l = __float2bfloat16(v - __bfloat162float(h));
        Th[(size_t)n * K + k] = h;
        Tl[(size_t)n * K + k] = l;
    }
}

// ---------------- split-bf16 mma.sync GEMM: C = A @ W (+R), fp32 in/out ----------
// A [M,K] fp32 row-major; Wh/Wl [N,K] bf16 row-major; C/R [M,N] fp32.
// CTA 128x128, BK=32, double-buffered smem, 8 warps (2x4), warp tile 64x32.
#define STG_BYTES 32768           // Ah 8K | Al 8K | Wh 8K | Wl 8K
#define GEMM_SMEM (2*STG_BYTES)

template<int EPI>
__global__ __launch_bounds__(256, 1)
void gemm_mma(const float* __restrict__ A, const __nv_bfloat16* __restrict__ Wh,
              const __nv_bfloat16* __restrict__ Wl, const float* __restrict__ R,
              float* __restrict__ C, int M, int N, int K)
{
    extern __shared__ char smc[];
    const int tid = threadIdx.x;
    const int wid = tid >> 5, lid = tid & 31;
    const int warpM = wid >> 2, warpN = wid & 3;
    const int row0 = blockIdx.y << 7, col0 = blockIdx.x << 7;
    const uint32_t sb = smem_u32(smc);

    // per-lane ldmatrix address constants (unswizzled base + XOR term)
    uint32_t aC[4], aM4[4];
    #pragma unroll
    for (int m = 0; m < 4; m++) {
        int r = warpM * 64 + m * 16 + (lid & 7) + (lid & 8);
        aC[m]  = ((uint32_t)(r >> 1) << 7) | ((uint32_t)(r & 1) << 6);
        aM4[m] = ((uint32_t)((r >> 1) & 7)) << 4;
    }
    const uint32_t aX = ((uint32_t)(lid >> 4)) << 4;
    uint32_t bC[2], bM4[2];
    #pragma unroll
    for (int p = 0; p < 2; p++) {
        int r = warpN * 32 + p * 16 + (lid & 7) + ((lid & 16) >> 1);
        bC[p]  = ((uint32_t)(r >> 1) << 7) | ((uint32_t)(r & 1) << 6);
        bM4[p] = ((uint32_t)((r >> 1) & 7)) << 4;
    }
    const uint32_t bX = ((uint32_t)((lid >> 3) & 1)) << 4;

    float acc[4][4][4];
    #pragma unroll
    for (int m = 0; m < 4; m++)
        #pragma unroll
        for (int n = 0; n < 4; n++)
            #pragma unroll
            for (int q = 0; q < 4; q++) acc[m][n][q] = 0.f;

    // loader mappings
    const int wr = tid >> 1;               // A row handled by this thread
    const int wcb = (tid & 1) * 16;        // A col base (fp32 elems)
    const int q0 = tid * 2;                // W 16B-chunk ids q0, q0+1

    const int nch = K >> 5;                // BK = 32

    auto issueW = [&](int kc, uint32_t ss){
        #pragma unroll
        for (int t2 = 0; t2 < 2; t2++) {
            int q = q0 + t2, r = q >> 2, c = q & 3;
            uint32_t o = tile_off(r, c * 16);
            const __nv_bfloat16* gh = Wh + (size_t)(col0 + r) * K + kc * 32 + c * 8;
            const __nv_bfloat16* gl = Wl + (size_t)(col0 + r) * K + kc * 32 + c * 8;
            cp16(sb + ss + 16384 + o, gh);
            cp16(sb + ss + 24576 + o, gl);
        }
    };
    float4 ar[4];
    auto ldgA = [&](int kc){
        const float* p = A + (size_t)(row0 + wr) * K + kc * 32 + wcb;
        #pragma unroll
        for (int j = 0; j < 4; j++) ar[j] = *(const float4*)(p + 4 * j);
    };
    auto stsA = [&](uint32_t ss){
        #pragma unroll
        for (int j = 0; j < 4; j++) {
            uint32_t h0, l0, h1, l1;
            split2(ar[j].x, ar[j].y, h0, l0);
            split2(ar[j].z, ar[j].w, h1, l1);
            uint32_t o = tile_off(wr, (wcb + 4 * j) * 2);
            *(uint2*)(smc + ss + o)        = make_uint2(h0, h1);
            *(uint2*)(smc + ss + 8192 + o) = make_uint2(l0, l1);
        }
    };
    auto compute = [&](uint32_t ss){
        uint32_t bAh = sb + ss, bAl = bAh + 8192, bWh = bAh + 16384, bWl = bAh + 24576;
        #pragma unroll
        for (int ks = 0; ks < 2; ks++) {
            const uint32_t kb = (uint32_t)ks << 5;
            uint32_t Af[16], Bh[8], Bl[8];
            // NOTE: swizzle XOR must apply to the full offset (incl. row-pair
            // bit 6) -- (base + byte) ^ M4, never base + (byte ^ M4).
            #pragma unroll
            for (int m = 0; m < 4; m++)
                ldsm4(Af[4*m], Af[4*m+1], Af[4*m+2], Af[4*m+3],
                      bAh + ((aC[m] + kb + aX) ^ aM4[m]));
            #pragma unroll
            for (int p = 0; p < 2; p++)
                ldsm4(Bh[4*p], Bh[4*p+1], Bh[4*p+2], Bh[4*p+3],
                      bWh + ((bC[p] + kb + bX) ^ bM4[p]));
            #pragma unroll
            for (int m = 0; m < 4; m++)
                #pragma unroll
                for (int n = 0; n < 4; n++)
                    mma16816(acc[m][n], Af[4*m], Af[4*m+1], Af[4*m+2], Af[4*m+3], Bh[2*n], Bh[2*n+1]);
            #pragma unroll
            for (int p = 0; p < 2; p++)
                ldsm4(Bl[4*p], Bl[4*p+1], Bl[4*p+2], Bl[4*p+3],
                      bWl + ((bC[p] + kb + bX) ^ bM4[p]));
            #pragma unroll
            for (int m = 0; m < 4; m++)
                #pragma unroll
                for (int n = 0; n < 4; n++)
                    mma16816(acc[m][n], Af[4*m], Af[4*m+1], Af[4*m+2], Af[4*m+3], Bl[2*n], Bl[2*n+1]);
            #pragma unroll
            for (int m = 0; m < 4; m++)
                ldsm4(Af[4*m], Af[4*m+1], Af[4*m+2], Af[4*m+3],
                      bAl + ((aC[m] + kb + aX) ^ aM4[m]));
            #pragma unroll
            for (int m = 0; m < 4; m++)
                #pragma unroll
                for (int n = 0; n < 4; n++)
                    mma16816(acc[m][n], Af[4*m], Af[4*m+1], Af[4*m+2], Af[4*m+3], Bh[2*n], Bh[2*n+1]);
        }
    };

    // prologue: chunk 0 -> stage 0
    issueW(0, 0); CP_COMMIT();
    ldgA(0);
    stsA(0);
    CP_WAIT0();
    __syncthreads();

    for (int i = 0; i < nch; i++) {
        uint32_t ss = (uint32_t)(i & 1) * STG_BYTES;
        uint32_t sn = ss ^ STG_BYTES;
        if (i + 1 < nch) { issueW(i + 1, sn); CP_COMMIT(); ldgA(i + 1); }
        compute(ss);
        if (i + 1 < nch) { stsA(sn); CP_WAIT0(); }
        __syncthreads();
    }

    // epilogue
    const int erow = row0 + warpM * 64 + (lid >> 2);
    const int ecol = col0 + warpN * 32 + (lid & 3) * 2;
    #pragma unroll
    for (int m = 0; m < 4; m++) {
        #pragma unroll
        for (int n = 0; n < 4; n++) {
            int r = erow + m * 16, c = ecol + n * 8;
            float2 v0 = make_float2(acc[m][n][0], acc[m][n][1]);
            float2 v1 = make_float2(acc[m][n][2], acc[m][n][3]);
            if (EPI) {
                float2 r0 = *(const float2*)(R + (size_t)r * N + c);
                float2 r1 = *(const float2*)(R + (size_t)(r + 8) * N + c);
                v0.x += r0.x; v0.y += r0.y; v1.x += r1.x; v1.y += r1.y;
            }
            *(float2*)(C + (size_t)r * N + c) = v0;
            *(float2*)(C + (size_t)(r + 8) * N + c) = v1;
        }
    }
}

// ---------------- RoPE (in place on q and k) ----------------
__global__ void rope_kernel(float* __restrict__ q, float* __restrict__ k,
                            const float* __restrict__ fcos, const float* __restrict__ fsin)
{
    long idx = (long)blockIdx.x * blockDim.x + threadIdx.x;
    const long total = (long)M_TOK * (NH + NKV) * (HEAD / 2);
    if (idx >= total) return;
    int j  = idx & 63;
    long t2 = idx >> 6;
    int hh = (int)(t2 % (NH + NKV));
    long tok = t2 / (NH + NKV);
    int s = (int)(tok % SEQ);

    float* p;
    if (hh < NH) p = q + ((size_t)tok * NH + hh) * HEAD + 2 * j;
    else         p = k + ((size_t)tok * NKV + (hh - NH)) * HEAD + 2 * j;

    float c = fcos[s * 64 + j];
    float sn = fsin[s * 64 + j];
    float x0 = p[0], x1 = p[1];
    p[0] = x0 * c - x1 * sn;
    p[1] = x0 * sn + x1 * c;
}

// ---------------- flash attention (fp32, causal, GQA) ----------------
#define QT 64
#define KT 64
#define PQK 130
#define PVS 132

__global__ __launch_bounds__(256, 1)
void flash_kernel(const float* __restrict__ Q, const float* __restrict__ K,
                  const float* __restrict__ V, float* __restrict__ O)
{
    extern __shared__ float sm[];
    float* Qs = sm;
    float* Ks = Qs + QT * PQK;
    float* Vs = Ks + KT * PQK;
    float* Ps = Vs + KT * PVS;

    const int t  = threadIdx.x;
    const int bx = blockIdx.x;
    const int h  = blockIdx.y;
    const int b  = blockIdx.z;
    const int kvh = h >> 2;
    const int q0 = bx * QT;
    const float scale = 0.08838834764831845f;

    {
        const float* qbase = Q + ((size_t)(b * SEQ + q0) * NH + h) * HEAD;
        for (int e = t; e < QT * 64; e += 256) {
            int r = e >> 6, cc = (e & 63) << 1;
            float2 v = *(const float2*)(qbase + (size_t)r * NH * HEAD + cc);
            Qs[r * PQK + cc]     = v.x;
            Qs[r * PQK + cc + 1] = v.y;
        }
    }

    const int pq = t >> 2;
    const int pd = (t & 3) * 4;
    const int sq0 = (t >> 4) * 4;
    const int scc = t & 15;

    float m = -INFINITY, l = 0.f;
    float4 acc[8];
    #pragma unroll
    for (int c = 0; c < 8; c++) acc[c] = make_float4(0.f, 0.f, 0.f, 0.f);

    for (int j = 0; j <= bx; j++) {
        __syncthreads();
        {
            const float* kbase = K + ((size_t)(b * SEQ + j * KT) * NKV + kvh) * HEAD;
            const float* vbase = V + ((size_t)(b * SEQ + j * KT) * NKV + kvh) * HEAD;
            for (int e = t; e < KT * 64; e += 256) {
                int r = e >> 6, cc = (e & 63) << 1;
                float2 kv2 = *(const float2*)(kbase + (size_t)r * NKV * HEAD + cc);
                Ks[r * PQK + cc]     = kv2.x;
                Ks[r * PQK + cc + 1] = kv2.y;
                float2 vv2 = *(const float2*)(vbase + (size_t)r * NKV * HEAD + cc);
                Vs[r * PVS + cc]     = vv2.x;
                Vs[r * PVS + cc + 1] = vv2.y;
            }
        }
        __syncthreads();

        float s4[4][4];
        #pragma unroll
        for (int i = 0; i < 4; i++)
            #pragma unroll
            for (int mm = 0; mm < 4; mm++) s4[i][mm] = 0.f;

        for (int d = 0; d < HEAD; d++) {
            float qv[4], kv[4];
            #pragma unroll
            for (int i = 0; i < 4; i++) qv[i] = Qs[(sq0 + i) * PQK + d];
            #pragma unroll
            for (int mm = 0; mm < 4; mm++) kv[mm] = Ks[(scc + 16 * mm) * PQK + d];
            #pragma unroll
            for (int i = 0; i < 4; i++)
                #pragma unroll
                for (int mm = 0; mm < 4; mm++) s4[i][mm] += qv[i] * kv[mm];
        }
        const bool diag = (j == bx);
        #pragma unroll
        for (int i = 0; i < 4; i++) {
            #pragma unroll
            for (int mm = 0; mm < 4; mm++) {
                float sv = s4[i][mm] * scale;
                if (diag && (j * KT + scc + 16 * mm) > (q0 + sq0 + i)) sv = -1e30f;
                Ps[(sq0 + i) * 65 + scc + 16 * mm] = sv;
            }
        }
        __syncthreads();

        float tmax = -1e30f;
        #pragma unroll
        for (int k4 = 0; k4 < 16; k4++)
            tmax = fmaxf(tmax, Ps[pq * 65 + (t & 3) + 4 * k4]);
        tmax = fmaxf(tmax, __shfl_xor_sync(0xffffffffu, tmax, 1));
        tmax = fmaxf(tmax, __shfl_xor_sync(0xffffffffu, tmax, 2));
        float mnew = fmaxf(m, tmax);
        float psum = 0.f;
        #pragma unroll
        for (int k4 = 0; k4 < 16; k4++) {
            int si = (t & 3) + 4 * k4;
            float p = __expf(Ps[pq * 65 + si] - mnew);
            Ps[pq * 65 + si] = p;
            psum += p;
        }
        psum += __shfl_xor_sync(0xffffffffu, psum, 1);
        psum += __shfl_xor_sync(0xffffffffu, psum, 2);
        float sc_old = __expf(m - mnew);
        l = l * sc_old + psum;
        m = mnew;
        #pragma unroll
        for (int c = 0; c < 8; c++) {
            acc[c].x *= sc_old; acc[c].y *= sc_old;
            acc[c].z *= sc_old; acc[c].w *= sc_old;
        }
        __syncthreads();

        for (int s = 0; s < KT; s++) {
            float p = Ps[pq * 65 + s];
            #pragma unroll
            for (int c = 0; c < 8; c++) {
                float4 v4 = *(const float4*)&Vs[s * PVS + pd + 16 * c];
                acc[c].x += p * v4.x; acc[c].y += p * v4.y;
                acc[c].z += p * v4.z; acc[c].w += p * v4.w;
            }
        }
    }

    float inv = 1.f / l;
    float* obase = O + ((size_t)(b * SEQ + q0 + pq) * NH + h) * HEAD;
    #pragma unroll
    for (int c = 0; c < 8; c++) {
        float4 v = acc[c];
        v.x *= inv; v.y *= inv; v.z *= inv; v.w *= inv;
        *(float4*)(obase + pd + 16 * c) = v;
    }
}

// ---------------- silu(gate) * up, in place into gate ----------------
__global__ void silu_mul_kernel(float* __restrict__ g, const float* __restrict__ u, long n4)
{
    long i = (long)blockIdx.x * blockDim.x + threadIdx.x;
    if (i >= n4) return;
    float4 gv = ((const float4*)g)[i];
    float4 uv = ((const float4*)u)[i];
    gv.x = gv.x / (1.f + __expf(-gv.x)) * uv.x;
    gv.y = gv.y / (1.f + __expf(-gv.y)) * uv.y;
    gv.z = gv.z / (1.f + __expf(-gv.z)) * uv.z;
    gv.w = gv.w / (1.f + __expf(-gv.w)) * uv.w;
    ((float4*)g)[i] = gv;
}

// ---------------- host launcher ----------------
extern "C" void kernel_launch(void* const* d_in, const int* in_sizes, int n_in,
                              void* d_out, int out_size)
{
    const float* x    = (const float*)d_in[0];
    const float* fcos = (const float*)d_in[2];
    const float* fsin = (const float*)d_in[3];
    const float* wq   = (const float*)d_in[4];
    const float* wk   = (const float*)d_in[5];
    const float* wv   = (const float*)d_in[6];
    const float* wo   = (const float*)d_in[7];
    const float* w1   = (const float*)d_in[8];
    const float* w2   = (const float*)d_in[9];
    const float* w3   = (const float*)d_in[10];
    float* out = (float*)d_out;

    float *xq, *xk, *xv, *attn, *h, *gate, *up;
    cudaGetSymbolAddress((void**)&xq,   g_xq);
    cudaGetSymbolAddress((void**)&xk,   g_xk);
    cudaGetSymbolAddress((void**)&xv,   g_xv);
    cudaGetSymbolAddress((void**)&attn, g_attn);
    cudaGetSymbolAddress((void**)&h,    g_h);
    cudaGetSymbolAddress((void**)&gate, g_gate);
    cudaGetSymbolAddress((void**)&up,   g_up);

    __nv_bfloat16 *wqh,*wql,*wkh,*wkl,*wvh,*wvl,*woh,*wol,*w1h,*w1l,*w3h,*w3l,*w2h,*w2l;
    cudaGetSymbolAddress((void**)&wqh, g_wq_h); cudaGetSymbolAddress((void**)&wql, g_wq_l);
    cudaGetSymbolAddress((void**)&wkh, g_wk_h); cudaGetSymbolAddress((void**)&wkl, g_wk_l);
    cudaGetSymbolAddress((void**)&wvh, g_wv_h); cudaGetSymbolAddress((void**)&wvl, g_wv_l);
    cudaGetSymbolAddress((void**)&woh, g_wo_h); cudaGetSymbolAddress((void**)&wol, g_wo_l);
    cudaGetSymbolAddress((void**)&w1h, g_w1_h); cudaGetSymbolAddress((void**)&w1l, g_w1_l);
    cudaGetSymbolAddress((void**)&w3h, g_w3_h); cudaGetSymbolAddress((void**)&w3l, g_w3_l);
    cudaGetSymbolAddress((void**)&w2h, g_w2_h); cudaGetSymbolAddress((void**)&w2l, g_w2_l);

    const int FL_SMEM = (QT * PQK + KT * PQK + KT * PVS + 64 * 65) * 4;
    cudaFuncSetAttribute(flash_kernel, cudaFuncAttributeMaxDynamicSharedMemorySize, FL_SMEM);
    cudaFuncSetAttribute(gemm_mma<0>, cudaFuncAttributeMaxDynamicSharedMemorySize, GEMM_SMEM);
    cudaFuncSetAttribute(gemm_mma<1>, cudaFuncAttributeMaxDynamicSharedMemorySize, GEMM_SMEM);

    // weight transpose + split (per launch; ~1.4GB traffic)
    dim3 cb(32, 8);
    conv_w_kernel<<<dim3(4096/32, 4096/32), cb>>>(wq, wqh, wql, DIM, NH*HEAD);
    conv_w_kernel<<<dim3(1024/32, 4096/32), cb>>>(wk, wkh, wkl, DIM, NKV*HEAD);
    conv_w_kernel<<<dim3(1024/32, 4096/32), cb>>>(wv, wvh, wvl, DIM, NKV*HEAD);
    conv_w_kernel<<<dim3(4096/32, 4096/32), cb>>>(wo, woh, wol, NH*HEAD, DIM);
    conv_w_kernel<<<dim3(HIDDEN/32, 4096/32), cb>>>(w1, w1h, w1l, DIM, HIDDEN);
    conv_w_kernel<<<dim3(HIDDEN/32, 4096/32), cb>>>(w3, w3h, w3l, DIM, HIDDEN);
    conv_w_kernel<<<dim3(4096/32, HIDDEN/32), cb>>>(w2, w2h, w2l, HIDDEN, DIM);

    // QKV projections
    gemm_mma<0><<<dim3(32, 32), 256, GEMM_SMEM>>>(x, wqh, wql, nullptr, xq, M_TOK, NH*HEAD, DIM);
    gemm_mma<0><<<dim3(8, 32), 256, GEMM_SMEM>>>(x, wkh, wkl, nullptr, xk, M_TOK, NKV*HEAD, DIM);
    gemm_mma<0><<<dim3(8, 32), 256, GEMM_SMEM>>>(x, wvh, wvl, nullptr, xv, M_TOK, NKV*HEAD, DIM);

    // RoPE
    {
        long total = (long)M_TOK * (NH + NKV) * (HEAD / 2);
        int blocks = (int)((total + 255) / 256);
        rope_kernel<<<blocks, 256>>>(xq, xk, fcos, fsin);
    }

    // attention
    flash_kernel<<<dim3(SEQ / QT, NH, B_SZ), 256, FL_SMEM>>>(xq, xk, xv, attn);

    // output projection + residual: h = x + attn @ wo
    gemm_mma<1><<<dim3(32, 32), 256, GEMM_SMEM>>>(attn, woh, wol, x, h, M_TOK, DIM, NH*HEAD);

    // FFN
    gemm_mma<0><<<dim3(HIDDEN/128, 32), 256, GEMM_SMEM>>>(h, w1h, w1l, nullptr, gate, M_TOK, HIDDEN, DIM);
    gemm_mma<0><<<dim3(HIDDEN/128, 32), 256, GEMM_SMEM>>>(h, w3h, w3l, nullptr, up, M_TOK, HIDDEN, DIM);
    {
        long n4 = (long)M_TOK * HIDDEN / 4;
        int blocks = (int)((n4 + 255) / 256);
        silu_mul_kernel<<<blocks, 256>>>(gate, up, n4);
    }
    // out = h + (silu(g)*u) @ w2
    gemm_mma<1><<<dim3(32, 32), 256, GEMM_SMEM>>>(gate, w2h, w2l, h, out, M_TOK, DIM, HIDDEN);
}

// round 12
// speedup vs baseline: 2.0673x; 1.1035x over previous
#include <cuda_runtime.h>
#include <cuda_bf16.h>
#include <math.h>
#include <stdint.h>

#define B_SZ 2
#define SEQ 2048
#define DIM 4096
#define NH 32
#define NKV 8
#define HEAD 128
#define HIDDEN 11008
#define M_TOK (B_SZ*SEQ)   // 4096

// ---------------- scratch (device globals; allocation-free rule) ----------------
__device__ float g_xq  [(size_t)M_TOK * NH  * HEAD];
__device__ float g_xk  [(size_t)M_TOK * NKV * HEAD];
__device__ float g_xv  [(size_t)M_TOK * NKV * HEAD];
__device__ float g_h   [(size_t)M_TOK * DIM];
__device__ float g_gate[(size_t)M_TOK * HIDDEN];
__device__ float g_up  [(size_t)M_TOK * HIDDEN];

// split activations (bf16 hi/lo)
__device__ __nv_bfloat16 g_xh[(size_t)M_TOK*DIM],     g_xl[(size_t)M_TOK*DIM];
__device__ __nv_bfloat16 g_ah[(size_t)M_TOK*DIM],     g_al[(size_t)M_TOK*DIM];      // attn
__device__ __nv_bfloat16 g_hh[(size_t)M_TOK*DIM],     g_hl[(size_t)M_TOK*DIM];
__device__ __nv_bfloat16 g_gh[(size_t)M_TOK*HIDDEN],  g_gl[(size_t)M_TOK*HIDDEN];

// transposed + split weights: T[n][k] = split(W[k][n]), bf16 hi/lo
__device__ __nv_bfloat16 g_wq_h[(size_t)DIM*NH*HEAD],  g_wq_l[(size_t)DIM*NH*HEAD];
__device__ __nv_bfloat16 g_wk_h[(size_t)DIM*NKV*HEAD], g_wk_l[(size_t)DIM*NKV*HEAD];
__device__ __nv_bfloat16 g_wv_h[(size_t)DIM*NKV*HEAD], g_wv_l[(size_t)DIM*NKV*HEAD];
__device__ __nv_bfloat16 g_wo_h[(size_t)DIM*NH*HEAD],  g_wo_l[(size_t)DIM*NH*HEAD];
__device__ __nv_bfloat16 g_w1_h[(size_t)DIM*HIDDEN],   g_w1_l[(size_t)DIM*HIDDEN];
__device__ __nv_bfloat16 g_w3_h[(size_t)DIM*HIDDEN],   g_w3_l[(size_t)DIM*HIDDEN];
__device__ __nv_bfloat16 g_w2_h[(size_t)DIM*HIDDEN],   g_w2_l[(size_t)DIM*HIDDEN];

// ---------------- helpers (sm_80-compatible only) ----------------
__device__ __forceinline__ uint32_t smem_u32(const void* p){
    uint32_t a;
    asm("{ .reg .u64 t; cvta.to.shared.u64 t, %1; cvt.u32.u64 %0, t; }" : "=r"(a) : "l"(p));
    return a;
}
__device__ __forceinline__ void cp16(uint32_t dst, const void* src){
    asm volatile("cp.async.cg.shared.global [%0], [%1], 16;" :: "r"(dst), "l"(src) : "memory");
}
#define CP_COMMIT() asm volatile("cp.async.commit_group;" ::: "memory")
#define CP_WAIT2()  asm volatile("cp.async.wait_group 2;" ::: "memory")

__device__ __forceinline__ void ldsm4(uint32_t& r0, uint32_t& r1, uint32_t& r2, uint32_t& r3, uint32_t a){
    asm volatile("ldmatrix.sync.aligned.m8n8.x4.shared.b16 {%0,%1,%2,%3}, [%4];"
                 : "=r"(r0), "=r"(r1), "=r"(r2), "=r"(r3) : "r"(a));
}
__device__ __forceinline__ void mma16816(float* c, uint32_t a0, uint32_t a1, uint32_t a2, uint32_t a3,
                                         uint32_t b0, uint32_t b1){
    asm volatile("mma.sync.aligned.m16n8k16.row.col.f32.bf16.bf16.f32 "
                 "{%0,%1,%2,%3}, {%4,%5,%6,%7}, {%8,%9}, {%0,%1,%2,%3};"
                 : "+f"(c[0]), "+f"(c[1]), "+f"(c[2]), "+f"(c[3])
                 : "r"(a0), "r"(a1), "r"(a2), "r"(a3), "r"(b0), "r"(b1));
}
__device__ __forceinline__ void split2(float x, float y, uint32_t& h, uint32_t& l){
    __nv_bfloat16 hx = __float2bfloat16(x), hy = __float2bfloat16(y);
    float rx = x - __bfloat162float(hx), ry = y - __bfloat162float(hy);
    __nv_bfloat16 lx = __float2bfloat16(rx), ly = __float2bfloat16(ry);
    h = ((uint32_t)__bfloat16_as_ushort(hy) << 16) | __bfloat16_as_ushort(hx);
    l = ((uint32_t)__bfloat16_as_ushort(ly) << 16) | __bfloat16_as_ushort(lx);
}
// tile: 128 logical rows x 64B; row pairs share a 128B physical row; XOR swizzle bits [4:6].
__device__ __forceinline__ uint32_t tile_off(int r, int byte_in_row){
    uint32_t o = ((uint32_t)(r >> 1) << 7) + ((uint32_t)(r & 1) << 6) + (uint32_t)byte_in_row;
    return o ^ ((o >> 3) & 0x70);
}

// ---------------- all-weights transpose + hi/lo split (single launch) ----------------
struct ConvJobs {
    const float* W[7];
    __nv_bfloat16 *Th[7], *Tl[7];
    int K[7], N[7];
    int off[8];
};
__global__ void conv_w_all(ConvJobs jobs)
{
    __shared__ float tile[32][33];
    int bid = blockIdx.x;
    int j = 0;
    #pragma unroll
    for (int t = 0; t < 7; t++) if (bid >= jobs.off[t + 1]) j = t + 1;
    int local = bid - jobs.off[j];
    const int K = jobs.K[j], N = jobs.N[j];
    int nb = N >> 5;
    int n0 = (local % nb) << 5, k0 = (local / nb) << 5;
    const float* W = jobs.W[j];
    __nv_bfloat16* Th = jobs.Th[j];
    __nv_bfloat16* Tl = jobs.Tl[j];
    int tx = threadIdx.x, ty = threadIdx.y;   // 32 x 8
    #pragma unroll
    for (int r = 0; r < 32; r += 8)
        tile[ty + r][tx] = W[(size_t)(k0 + ty + r) * N + n0 + tx];
    __syncthreads();
    #pragma unroll
    for (int r = 0; r < 32; r += 8) {
        int n = n0 + ty + r, k = k0 + tx;
        float v = tile[tx][ty + r];
        __nv_bfloat16 h = __float2bfloat16(v);
        __nv_bfloat16 l = __float2bfloat16(v - __bfloat162float(h));
        Th[(size_t)n * K + k] = h;
        Tl[(size_t)n * K + k] = l;
    }
}

// ---------------- activation split: fp32 -> bf16 hi/lo ----------------
__global__ void split_kernel(const float* __restrict__ X, __nv_bfloat16* __restrict__ Xh,
                             __nv_bfloat16* __restrict__ Xl, long n4)
{
    long i = (long)blockIdx.x * blockDim.x + threadIdx.x;
    if (i >= n4) return;
    float4 v = ((const float4*)X)[i];
    uint32_t h0, l0, h1, l1;
    split2(v.x, v.y, h0, l0);
    split2(v.z, v.w, h1, l1);
    ((uint2*)Xh)[i] = make_uint2(h0, h1);
    ((uint2*)Xl)[i] = make_uint2(l0, l1);
}

// ---------------- split-bf16 mma.sync GEMM ----------------
// MODE 0: C = A@W ; MODE 1: C = A@W + R ; MODE 2: C = rope(A@W) ;
// MODE 3: C = A@W + R, plus split output Ch/Cl.
#define STG_BYTES 32768           // Ah 8K | Al 8K | Wh 8K | Wl 8K
#define STAGES 4
#define GEMM_SMEM (STAGES*STG_BYTES)

template<int MODE>
__global__ __launch_bounds__(256, 1)
void gemm_mma(const __nv_bfloat16* __restrict__ Ah, const __nv_bfloat16* __restrict__ Al,
              const __nv_bfloat16* __restrict__ Wh, const __nv_bfloat16* __restrict__ Wl,
              const float* __restrict__ R, float* __restrict__ C,
              __nv_bfloat16* __restrict__ Ch, __nv_bfloat16* __restrict__ Cl,
              const float* __restrict__ fcos, const float* __restrict__ fsin,
              int M, int N, int K)
{
    extern __shared__ char smc[];
    const int tid = threadIdx.x;
    const int wid = tid >> 5, lid = tid & 31;
    const int warpM = wid >> 2, warpN = wid & 3;
    const int row0 = blockIdx.y << 7, col0 = blockIdx.x << 7;
    const uint32_t sb = smem_u32(smc);

    uint32_t aC[4], aM4[4];
    #pragma unroll
    for (int m = 0; m < 4; m++) {
        int r = warpM * 64 + m * 16 + (lid & 7) + (lid & 8);
        aC[m]  = ((uint32_t)(r >> 1) << 7) | ((uint32_t)(r & 1) << 6);
        aM4[m] = ((uint32_t)((r >> 1) & 7)) << 4;
    }
    const uint32_t aX = ((uint32_t)(lid >> 4)) << 4;
    uint32_t bC[2], bM4[2];
    #pragma unroll
    for (int p = 0; p < 2; p++) {
        int r = warpN * 32 + p * 16 + (lid & 7) + ((lid & 16) >> 1);
        bC[p]  = ((uint32_t)(r >> 1) << 7) | ((uint32_t)(r & 1) << 6);
        bM4[p] = ((uint32_t)((r >> 1) & 7)) << 4;
    }
    const uint32_t bX = ((uint32_t)((lid >> 3) & 1)) << 4;

    float acc[4][4][4];
    #pragma unroll
    for (int m = 0; m < 4; m++)
        #pragma unroll
        for (int n = 0; n < 4; n++)
            #pragma unroll
            for (int q = 0; q < 4; q++) acc[m][n][q] = 0.f;

    const int nch = K >> 5;                 // BK = 32

    // loader: q = tid*2 + {0,1}; r = q>>2 (row), c = q&3 (16B chunk)
    auto issue = [&](int kc, int st){
        uint32_t ss = (uint32_t)st * STG_BYTES;
        #pragma unroll
        for (int t2 = 0; t2 < 2; t2++) {
            int q = tid * 2 + t2, r = q >> 2, c = q & 3;
            uint32_t o = tile_off(r, c * 16);
            size_t ga = (size_t)(row0 + r) * K + (size_t)kc * 32 + c * 8;
            size_t gw = (size_t)(col0 + r) * K + (size_t)kc * 32 + c * 8;
            cp16(sb + ss + o,         Ah + ga);
            cp16(sb + ss + 8192 + o,  Al + ga);
            cp16(sb + ss + 16384 + o, Wh + gw);
            cp16(sb + ss + 24576 + o, Wl + gw);
        }
    };
    auto compute = [&](int st){
        uint32_t bAh = sb + (uint32_t)st * STG_BYTES;
        uint32_t bAl = bAh + 8192, bWh = bAh + 16384, bWl = bAh + 24576;
        #pragma unroll
        for (int ks = 0; ks < 2; ks++) {
            const uint32_t kb = (uint32_t)ks << 5;
            uint32_t Af[16], Bh[8], Bl[8];
            #pragma unroll
            for (int m = 0; m < 4; m++)
                ldsm4(Af[4*m], Af[4*m+1], Af[4*m+2], Af[4*m+3],
                      bAh + ((aC[m] + kb + aX) ^ aM4[m]));
            #pragma unroll
            for (int p = 0; p < 2; p++)
                ldsm4(Bh[4*p], Bh[4*p+1], Bh[4*p+2], Bh[4*p+3],
                      bWh + ((bC[p] + kb + bX) ^ bM4[p]));
            #pragma unroll
            for (int m = 0; m < 4; m++)
                #pragma unroll
                for (int n = 0; n < 4; n++)
                    mma16816(acc[m][n], Af[4*m], Af[4*m+1], Af[4*m+2], Af[4*m+3], Bh[2*n], Bh[2*n+1]);
            #pragma unroll
            for (int p = 0; p < 2; p++)
                ldsm4(Bl[4*p], Bl[4*p+1], Bl[4*p+2], Bl[4*p+3],
                      bWl + ((bC[p] + kb + bX) ^ bM4[p]));
            #pragma unroll
            for (int m = 0; m < 4; m++)
                #pragma unroll
                for (int n = 0; n < 4; n++)
                    mma16816(acc[m][n], Af[4*m], Af[4*m+1], Af[4*m+2], Af[4*m+3], Bl[2*n], Bl[2*n+1]);
            #pragma unroll
            for (int m = 0; m < 4; m++)
                ldsm4(Af[4*m], Af[4*m+1], Af[4*m+2], Af[4*m+3],
                      bAl + ((aC[m] + kb + aX) ^ aM4[m]));
            #pragma unroll
            for (int m = 0; m < 4; m++)
                #pragma unroll
                for (int n = 0; n < 4; n++)
                    mma16816(acc[m][n], Af[4*m], Af[4*m+1], Af[4*m+2], Af[4*m+3], Bh[2*n], Bh[2*n+1]);
        }
    };

    // prologue: 3 stages in flight
    issue(0, 0); CP_COMMIT();
    issue(1, 1); CP_COMMIT();
    issue(2, 2); CP_COMMIT();

    for (int i = 0; i < nch; i++) {
        CP_WAIT2();            // chunk i's group complete
        __syncthreads();
        if (i + 3 < nch) { issue(i + 3, (i + 3) & 3); CP_COMMIT(); }
        compute(i & 3);
    }

    // epilogue
    const int erow = row0 + warpM * 64 + (lid >> 2);
    const int ecol = col0 + warpN * 32 + (lid & 3) * 2;
    #pragma unroll
    for (int m = 0; m < 4; m++) {
        #pragma unroll
        for (int n = 0; n < 4; n++) {
            int r = erow + m * 16, c = ecol + n * 8;
            float2 v0 = make_float2(acc[m][n][0], acc[m][n][1]);
            float2 v1 = make_float2(acc[m][n][2], acc[m][n][3]);
            if (MODE == 1 || MODE == 3) {
                float2 r0 = *(const float2*)(R + (size_t)r * N + c);
                float2 r1 = *(const float2*)(R + (size_t)(r + 8) * N + c);
                v0.x += r0.x; v0.y += r0.y; v1.x += r1.x; v1.y += r1.y;
            }
            if (MODE == 2) {
                int j = (c & 127) >> 1;
                int s0 = r & (SEQ - 1), s1 = (r + 8) & (SEQ - 1);
                float c0 = fcos[s0 * 64 + j], sn0 = fsin[s0 * 64 + j];
                float c1 = fcos[s1 * 64 + j], sn1 = fsin[s1 * 64 + j];
                float2 t0 = v0, t1 = v1;
                v0.x = t0.x * c0 - t0.y * sn0; v0.y = t0.x * sn0 + t0.y * c0;
                v1.x = t1.x * c1 - t1.y * sn1; v1.y = t1.x * sn1 + t1.y * c1;
            }
            *(float2*)(C + (size_t)r * N + c) = v0;
            *(float2*)(C + (size_t)(r + 8) * N + c) = v1;
            if (MODE == 3) {
                uint32_t h0, l0, h1, l1;
                split2(v0.x, v0.y, h0, l0);
                split2(v1.x, v1.y, h1, l1);
                *(uint32_t*)((char*)Ch + ((size_t)r * N + c) * 2) = h0;
                *(uint32_t*)((char*)Cl + ((size_t)r * N + c) * 2) = l0;
                *(uint32_t*)((char*)Ch + ((size_t)(r + 8) * N + c) * 2) = h1;
                *(uint32_t*)((char*)Cl + ((size_t)(r + 8) * N + c) * 2) = l1;
            }
        }
    }
}

// ---------------- flash attention (fp32, causal, GQA; split bf16 output) ----------------
#define QT 64
#define KT 64
#define PQK 130
#define PVS 132

__global__ __launch_bounds__(256, 1)
void flash_kernel(const float* __restrict__ Q, const float* __restrict__ K,
                  const float* __restrict__ V,
                  __nv_bfloat16* __restrict__ Oh, __nv_bfloat16* __restrict__ Ol)
{
    extern __shared__ float sm[];
    float* Qs = sm;
    float* Ks = Qs + QT * PQK;
    float* Vs = Ks + KT * PQK;
    float* Ps = Vs + KT * PVS;

    const int t  = threadIdx.x;
    const int bx = blockIdx.x;
    const int h  = blockIdx.y;
    const int b  = blockIdx.z;
    const int kvh = h >> 2;
    const int q0 = bx * QT;
    const float scale = 0.08838834764831845f;

    {
        const float* qbase = Q + ((size_t)(b * SEQ + q0) * NH + h) * HEAD;
        for (int e = t; e < QT * 64; e += 256) {
            int r = e >> 6, cc = (e & 63) << 1;
            float2 v = *(const float2*)(qbase + (size_t)r * NH * HEAD + cc);
            Qs[r * PQK + cc]     = v.x;
            Qs[r * PQK + cc + 1] = v.y;
        }
    }

    const int pq = t >> 2;
    const int pd = (t & 3) * 4;
    const int sq0 = (t >> 4) * 4;
    const int scc = t & 15;

    float m = -INFINITY, l = 0.f;
    float4 acc[8];
    #pragma unroll
    for (int c = 0; c < 8; c++) acc[c] = make_float4(0.f, 0.f, 0.f, 0.f);

    for (int j = 0; j <= bx; j++) {
        __syncthreads();
        {
            const float* kbase = K + ((size_t)(b * SEQ + j * KT) * NKV + kvh) * HEAD;
            const float* vbase = V + ((size_t)(b * SEQ + j * KT) * NKV + kvh) * HEAD;
            for (int e = t; e < KT * 64; e += 256) {
                int r = e >> 6, cc = (e & 63) << 1;
                float2 kv2 = *(const float2*)(kbase + (size_t)r * NKV * HEAD + cc);
                Ks[r * PQK + cc]     = kv2.x;
                Ks[r * PQK + cc + 1] = kv2.y;
                float2 vv2 = *(const float2*)(vbase + (size_t)r * NKV * HEAD + cc);
                Vs[r * PVS + cc]     = vv2.x;
                Vs[r * PVS + cc + 1] = vv2.y;
            }
        }
        __syncthreads();

        float s4[4][4];
        #pragma unroll
        for (int i = 0; i < 4; i++)
            #pragma unroll
            for (int mm = 0; mm < 4; mm++) s4[i][mm] = 0.f;

        for (int d = 0; d < HEAD; d++) {
            float qv[4], kv[4];
            #pragma unroll
            for (int i = 0; i < 4; i++) qv[i] = Qs[(sq0 + i) * PQK + d];
            #pragma unroll
            for (int mm = 0; mm < 4; mm++) kv[mm] = Ks[(scc + 16 * mm) * PQK + d];
            #pragma unroll
            for (int i = 0; i < 4; i++)
                #pragma unroll
                for (int mm = 0; mm < 4; mm++) s4[i][mm] += qv[i] * kv[mm];
        }
        const bool diag = (j == bx);
        #pragma unroll
        for (int i = 0; i < 4; i++) {
            #pragma unroll
            for (int mm = 0; mm < 4; mm++) {
                float sv = s4[i][mm] * scale;
                if (diag && (j * KT + scc + 16 * mm) > (q0 + sq0 + i)) sv = -1e30f;
                Ps[(sq0 + i) * 65 + scc + 16 * mm] = sv;
            }
        }
        __syncthreads();

        float tmax = -1e30f;
        #pragma unroll
        for (int k4 = 0; k4 < 16; k4++)
            tmax = fmaxf(tmax, Ps[pq * 65 + (t & 3) + 4 * k4]);
        tmax = fmaxf(tmax, __shfl_xor_sync(0xffffffffu, tmax, 1));
        tmax = fmaxf(tmax, __shfl_xor_sync(0xffffffffu, tmax, 2));
        float mnew = fmaxf(m, tmax);
        float psum = 0.f;
        #pragma unroll
        for (int k4 = 0; k4 < 16; k4++) {
            int si = (t & 3) + 4 * k4;
            float p = __expf(Ps[pq * 65 + si] - mnew);
            Ps[pq * 65 + si] = p;
            psum += p;
        }
        psum += __shfl_xor_sync(0xffffffffu, psum, 1);
        psum += __shfl_xor_sync(0xffffffffu, psum, 2);
        float sc_old = __expf(m - mnew);
        l = l * sc_old + psum;
        m = mnew;
        #pragma unroll
        for (int c = 0; c < 8; c++) {
            acc[c].x *= sc_old; acc[c].y *= sc_old;
            acc[c].z *= sc_old; acc[c].w *= sc_old;
        }
        __syncthreads();

        for (int s = 0; s < KT; s++) {
            float p = Ps[pq * 65 + s];
            #pragma unroll
            for (int c = 0; c < 8; c++) {
                float4 v4 = *(const float4*)&Vs[s * PVS + pd + 16 * c];
                acc[c].x += p * v4.x; acc[c].y += p * v4.y;
                acc[c].z += p * v4.z; acc[c].w += p * v4.w;
            }
        }
    }

    float inv = 1.f / l;
    size_t base = ((size_t)(b * SEQ + q0 + pq) * NH + h) * HEAD;
    #pragma unroll
    for (int c = 0; c < 8; c++) {
        float4 v = acc[c];
        v.x *= inv; v.y *= inv; v.z *= inv; v.w *= inv;
        uint32_t h0, l0, h1, l1;
        split2(v.x, v.y, h0, l0);
        split2(v.z, v.w, h1, l1);
        size_t idx = base + pd + 16 * c;
        *(uint2*)((char*)Oh + idx * 2) = make_uint2(h0, h1);
        *(uint2*)((char*)Ol + idx * 2) = make_uint2(l0, l1);
    }
}

// ---------------- silu(gate) * up -> split bf16 output ----------------
__global__ void silu_mul_kernel(const float* __restrict__ g, const float* __restrict__ u,
                                __nv_bfloat16* __restrict__ Gh, __nv_bfloat16* __restrict__ Gl, long n4)
{
    long i = (long)blockIdx.x * blockDim.x + threadIdx.x;
    if (i >= n4) return;
    float4 gv = ((const float4*)g)[i];
    float4 uv = ((const float4*)u)[i];
    float4 o;
    o.x = gv.x / (1.f + __expf(-gv.x)) * uv.x;
    o.y = gv.y / (1.f + __expf(-gv.y)) * uv.y;
    o.z = gv.z / (1.f + __expf(-gv.z)) * uv.z;
    o.w = gv.w / (1.f + __expf(-gv.w)) * uv.w;
    uint32_t h0, l0, h1, l1;
    split2(o.x, o.y, h0, l0);
    split2(o.z, o.w, h1, l1);
    ((uint2*)Gh)[i] = make_uint2(h0, h1);
    ((uint2*)Gl)[i] = make_uint2(l0, l1);
}

// ---------------- host launcher ----------------
extern "C" void kernel_launch(void* const* d_in, const int* in_sizes, int n_in,
                              void* d_out, int out_size)
{
    const float* x    = (const float*)d_in[0];
    const float* fcos = (const float*)d_in[2];
    const float* fsin = (const float*)d_in[3];
    const float* wq   = (const float*)d_in[4];
    const float* wk   = (const float*)d_in[5];
    const float* wv   = (const float*)d_in[6];
    const float* wo   = (const float*)d_in[7];
    const float* w1   = (const float*)d_in[8];
    const float* w2   = (const float*)d_in[9];
    const float* w3   = (const float*)d_in[10];
    float* out = (float*)d_out;

    float *xq, *xk, *xv, *h, *gate, *up;
    cudaGetSymbolAddress((void**)&xq,   g_xq);
    cudaGetSymbolAddress((void**)&xk,   g_xk);
    cudaGetSymbolAddress((void**)&xv,   g_xv);
    cudaGetSymbolAddress((void**)&h,    g_h);
    cudaGetSymbolAddress((void**)&gate, g_gate);
    cudaGetSymbolAddress((void**)&up,   g_up);

    __nv_bfloat16 *xh,*xl,*ah,*al,*hh,*hl,*gh,*gl;
    cudaGetSymbolAddress((void**)&xh, g_xh); cudaGetSymbolAddress((void**)&xl, g_xl);
    cudaGetSymbolAddress((void**)&ah, g_ah); cudaGetSymbolAddress((void**)&al, g_al);
    cudaGetSymbolAddress((void**)&hh, g_hh); cudaGetSymbolAddress((void**)&hl, g_hl);
    cudaGetSymbolAddress((void**)&gh, g_gh); cudaGetSymbolAddress((void**)&gl, g_gl);

    __nv_bfloat16 *wqh,*wql,*wkh,*wkl,*wvh,*wvl,*woh,*wol,*w1h,*w1l,*w3h,*w3l,*w2h,*w2l;
    cudaGetSymbolAddress((void**)&wqh, g_wq_h); cudaGetSymbolAddress((void**)&wql, g_wq_l);
    cudaGetSymbolAddress((void**)&wkh, g_wk_h); cudaGetSymbolAddress((void**)&wkl, g_wk_l);
    cudaGetSymbolAddress((void**)&wvh, g_wv_h); cudaGetSymbolAddress((void**)&wvl, g_wv_l);
    cudaGetSymbolAddress((void**)&woh, g_wo_h); cudaGetSymbolAddress((void**)&wol, g_wo_l);
    cudaGetSymbolAddress((void**)&w1h, g_w1_h); cudaGetSymbolAddress((void**)&w1l, g_w1_l);
    cudaGetSymbolAddress((void**)&w3h, g_w3_h); cudaGetSymbolAddress((void**)&w3l, g_w3_l);
    cudaGetSymbolAddress((void**)&w2h, g_w2_h); cudaGetSymbolAddress((void**)&w2l, g_w2_l);

    const int FL_SMEM = (QT * PQK + KT * PQK + KT * PVS + 64 * 65) * 4;
    cudaFuncSetAttribute(flash_kernel, cudaFuncAttributeMaxDynamicSharedMemorySize, FL_SMEM);
    cudaFuncSetAttribute(gemm_mma<0>, cudaFuncAttributeMaxDynamicSharedMemorySize, GEMM_SMEM);
    cudaFuncSetAttribute(gemm_mma<1>, cudaFuncAttributeMaxDynamicSharedMemorySize, GEMM_SMEM);
    cudaFuncSetAttribute(gemm_mma<2>, cudaFuncAttributeMaxDynamicSharedMemorySize, GEMM_SMEM);
    cudaFuncSetAttribute(gemm_mma<3>, cudaFuncAttributeMaxDynamicSharedMemorySize, GEMM_SMEM);

    // (0) all weight transposes+splits in one launch
    {
        ConvJobs jobs;
        const float* Ws[7]   = {wq, wk, wv, wo, w1, w3, w2};
        __nv_bfloat16* Ths[7] = {wqh, wkh, wvh, woh, w1h, w3h, w2h};
        __nv_bfloat16* Tls[7] = {wql, wkl, wvl, wol, w1l, w3l, w2l};
        int Ks[7] = {DIM, DIM, DIM, NH*HEAD, DIM, DIM, HIDDEN};
        int Ns[7] = {NH*HEAD, NKV*HEAD, NKV*HEAD, DIM, HIDDEN, HIDDEN, DIM};
        jobs.off[0] = 0;
        for (int i2 = 0; i2 < 7; i2++) {
            jobs.W[i2] = Ws[i2]; jobs.Th[i2] = Ths[i2]; jobs.Tl[i2] = Tls[i2];
            jobs.K[i2] = Ks[i2]; jobs.N[i2] = Ns[i2];
            jobs.off[i2+1] = jobs.off[i2] + (Ns[i2] >> 5) * (Ks[i2] >> 5);
        }
        conv_w_all<<<jobs.off[7], dim3(32, 8)>>>(jobs);
    }
    // (1) split x
    split_kernel<<<(int)(((long)M_TOK*DIM/4 + 255)/256), 256>>>(x, xh, xl, (long)M_TOK*DIM/4);

    // (2,3) Q,K projections with fused RoPE; (4) V projection
    gemm_mma<2><<<dim3(32, 32), 256, GEMM_SMEM>>>(xh, xl, wqh, wql, nullptr, xq, nullptr, nullptr, fcos, fsin, M_TOK, NH*HEAD, DIM);
    gemm_mma<2><<<dim3(8, 32), 256, GEMM_SMEM>>>(xh, xl, wkh, wkl, nullptr, xk, nullptr, nullptr, fcos, fsin, M_TOK, NKV*HEAD, DIM);
    gemm_mma<0><<<dim3(8, 32), 256, GEMM_SMEM>>>(xh, xl, wvh, wvl, nullptr, xv, nullptr, nullptr, nullptr, nullptr, M_TOK, NKV*HEAD, DIM);

    // (5) attention -> split attn
    flash_kernel<<<dim3(SEQ / QT, NH, B_SZ), 256, FL_SMEM>>>(xq, xk, xv, ah, al);

    // (6) h = x + attn @ wo ; also emits split(h)
    gemm_mma<3><<<dim3(32, 32), 256, GEMM_SMEM>>>(ah, al, woh, wol, x, h, hh, hl, nullptr, nullptr, M_TOK, DIM, NH*HEAD);

    // (7,8) FFN up/gate
    gemm_mma<0><<<dim3(HIDDEN/128, 32), 256, GEMM_SMEM>>>(hh, hl, w1h, w1l, nullptr, gate, nullptr, nullptr, nullptr, nullptr, M_TOK, HIDDEN, DIM);
    gemm_mma<0><<<dim3(HIDDEN/128, 32), 256, GEMM_SMEM>>>(hh, hl, w3h, w3l, nullptr, up, nullptr, nullptr, nullptr, nullptr, M_TOK, HIDDEN, DIM);

    // (9) silu*up -> split
    {
        long n4 = (long)M_TOK * HIDDEN / 4;
        silu_mul_kernel<<<(int)((n4 + 255)/256), 256>>>(gate, up, gh, gl, n4);
    }
    // (10) out = h + (silu(g)*u) @ w2
    gemm_mma<1><<<dim3(32, 32), 256, GEMM_SMEM>>>(gh, gl, w2h, w2l, h, out, nullptr, nullptr, nullptr, nullptr, M_TOK, DIM, HIDDEN);
}